// round 14
// baseline (speedup 1.0000x reference)
#include <cuda_runtime.h>

typedef unsigned long long u64;

__device__ float4 g_c;  // {ta, tc, alpha/128, beta}

__device__ __forceinline__ float ex2f(float x) {
    float y;
    asm("ex2.approx.ftz.f32 %0, %1;" : "=f"(y) : "f"(x));
    return y;
}
__device__ __forceinline__ float cosf_hw(float x) {
    float y;
    asm("cos.approx.ftz.f32 %0, %1;" : "=f"(y) : "f"(x));
    return y;
}
__device__ __forceinline__ u64 pk2(float lo, float hi) {
    u64 r; asm("mov.b64 %0, {%1, %2};" : "=l"(r) : "f"(lo), "f"(hi)); return r;
}
__device__ __forceinline__ void upk2(float& lo, float& hi, u64 v) {
    asm("mov.b64 {%0, %1}, %2;" : "=f"(lo), "=f"(hi) : "l"(v));
}
__device__ __forceinline__ u64 f2fma(u64 a, u64 b, u64 c) {
    u64 r; asm("fma.rn.f32x2 %0, %1, %2, %3;" : "=l"(r) : "l"(a), "l"(b), "l"(c)); return r;
}
__device__ __forceinline__ u64 f2add(u64 a, u64 b) {
    u64 r; asm("add.rn.f32x2 %0, %1, %2;" : "=l"(r) : "l"(a), "l"(b)); return r;
}

// One block, 192 threads: warps 0-4 compute the five 32-length dot products,
// warp 5 loads Wo; fold + write the 4 collapsed scalars to g_c.
__global__ void precompute_kernel(const float* __restrict__ Wt, const float* __restrict__ bt,
                                  const float* __restrict__ Wq, const float* __restrict__ bq,
                                  const float* __restrict__ Wk, const float* __restrict__ bk,
                                  const float* __restrict__ Wv, const float* __restrict__ bv,
                                  const float* __restrict__ Wo, const float* __restrict__ bo) {
    __shared__ float sv[6][32];
    const int warp = threadIdx.x >> 5;
    const int lane = threadIdx.x & 31;

    if (warp < 6) {
        const int e = lane;
        float acc;
        if (warp == 5) {
            acc = Wo[e];
        } else {
            const float* M = (warp == 0 || warp == 3) ? Wq : ((warp == 1) ? Wk : Wv);
            const float* v = (warp < 3) ? Wt : bt;
            acc = 0.f;
#pragma unroll 16
            for (int d = 0; d < 32; d++)
                acc = fmaf(v[d], M[d * 32 + e], acc);
            if (warp == 3) acc += bq[e];
            if (warp == 4) acc += bv[e];
        }
        sv[warp][e] = acc;
    }
    __syncthreads();

    if (warp == 0) {
        const int e = lane;
        const float qv = sv[0][e], kv = sv[1][e], vv = sv[2][e];
        const float qb = sv[3][e], vb = sv[4][e], wo = sv[5][e];
        float a  = qv * kv;
        float c1 = qb * kv;
        float al = vv * wo;
        float be = vb * wo;
#pragma unroll
        for (int off = 16; off > 0; off >>= 1) {
            a  += __shfl_xor_sync(0xffffffffu, a,  off);
            c1 += __shfl_xor_sync(0xffffffffu, c1, off);
            al += __shfl_xor_sync(0xffffffffu, al, off);
            be += __shfl_xor_sync(0xffffffffu, be, off);
        }
        if (e == 0) {
            const float LOG2E = 1.4426950408889634f;
            const float INV_SQRT_D = 0.17677669529663687f;
            g_c = make_float4(a * INV_SQRT_D * LOG2E,
                              c1 * INV_SQRT_D * LOG2E,
                              al * (1.0f / 128.0f),
                              be + bo[0]);
        }
    }
}

// Per warp = TWO batch rows (sequential). Single-wave grid: 1024 blocks fit
// inside the 148 SM x 8 resident-block footprint, eliminating the 73%-full
// second wave. Quarter-interval Chebyshev per row (8 nodes/quarter), PDL on
// the weight-collapse precompute.
__global__ __launch_bounds__(256, 8) void attn_cheb4_kernel(
    const float* __restrict__ x, float* __restrict__ out, int B) {
    __shared__ float sx[8][2][128];
    __shared__ float At[64];    // At[j*8 + i]: DCT-8 weight of node j in coeff i

    const int tid = threadIdx.x;
    const int warp = tid >> 5;
    const int lane = tid & 31;
    const int rb = blockIdx.x * 16 + warp * 2;   // first of this warp's 2 rows

    const float PI16 = 0.19634954084936207f;  // pi/16

    // load both rows (coalesced float4 per lane per row)
    if (rb < B)
        reinterpret_cast<float4*>(sx[warp][0])[lane] =
            reinterpret_cast<const float4*>(x + (size_t)rb * 128)[lane];
    if (rb + 1 < B)
        reinterpret_cast<float4*>(sx[warp][1])[lane] =
            reinterpret_cast<const float4*>(x + (size_t)(rb + 1) * 128)[lane];

    // DCT-8 table (independent of g_c)
    if (tid < 64) {
        const int j = tid >> 3, i = tid & 7;
        const int K = (i * (2 * j + 1)) & 31;
        At[tid] = cosf_hw((float)K * PI16) * (i == 0 ? 0.125f : 0.25f);
    }
    __syncthreads();

    // Wait for precompute grid, then read collapsed weights (once for both rows)
    cudaGridDependencySynchronize();
    const float4 c = g_c;
    const float ta = c.x, tc = c.y, alpha = c.z, beta = c.w;

    const int ni = lane & 7;
    const float gam = cosf_hw((float)(2 * ni + 1) * PI16);  // node pos (row-indep)
    const int hbase = lane & 24;  // quarter base h*8

#pragma unroll 1
    for (int r = 0; r < 2; r++) {
        const int b = rb + r;
        if (b >= B) break;
        const float* s = sx[warp][r];
        const float4 xv = reinterpret_cast<const float4*>(s)[lane];

        // row max / min
        float mx = fmaxf(fmaxf(xv.x, xv.y), fmaxf(xv.z, xv.w));
        float mn = fminf(fminf(xv.x, xv.y), fminf(xv.z, xv.w));
#pragma unroll
        for (int off = 16; off > 0; off >>= 1) {
            mx = fmaxf(mx, __shfl_xor_sync(0xffffffffu, mx, off));
            mn = fminf(mn, __shfl_xor_sync(0xffffffffu, mn, off));
        }
        __syncwarp();

        // t range; 4 quarters of width qw = rad/2, radius rq = rad/4
        const float tA = fmaf(ta, mn, tc);
        const float tB = fmaf(ta, mx, tc);
        const float tlo = fminf(tA, tB);
        const float thi = fmaxf(tA, tB);
        const float rad = fmaxf(0.5f * (thi - tlo), 1e-5f);
        const float qw = 0.5f * rad;
        const float rq = 0.25f * rad;
        const float invqw = __fdividef(1.0f, qw);
        const float invrq = 2.0f * invqw;

        // this lane's node
        const float cq = fmaf((float)(lane >> 3) + 0.5f, qw, tlo);
        const float tj = fmaf(rq, gam, cq);
        const float stab = -((tj > 0.f) ? tj * mx : tj * mn);

        // ---- exact node evaluation (packed f32x2) ----
        const u64 tjp = pk2(tj, tj);
        const u64 stp = pk2(stab, stab);
        u64 se2 = 0ull, sa2 = 0ull;
#pragma unroll 8
        for (int k = 0; k < 128; k += 4) {
            const float4 xg = *reinterpret_cast<const float4*>(s + k);
            {
                const u64 xp = pk2(xg.x, xg.y);
                const u64 zp = f2fma(tjp, xp, stp);
                float z0, z1;
                upk2(z0, z1, zp);
                const u64 ep = pk2(ex2f(z0), ex2f(z1));
                se2 = f2add(se2, ep);
                sa2 = f2fma(xp, ep, sa2);
            }
            {
                const u64 xp = pk2(xg.z, xg.w);
                const u64 zp = f2fma(tjp, xp, stp);
                float z0, z1;
                upk2(z0, z1, zp);
                const u64 ep = pk2(ex2f(z0), ex2f(z1));
                se2 = f2add(se2, ep);
                sa2 = f2fma(xp, ep, sa2);
            }
        }
        float lo, hi;
        upk2(lo, hi, se2); const float se = lo + hi;
        upk2(lo, hi, sa2); const float sa = lo + hi;
        const float mj = __fdividef(sa, se);

        // ---- DCT-8 per quarter ----
        float ci = 0.f;
#pragma unroll
        for (int j = 0; j < 8; j++) {
            const float mjj = __shfl_sync(0xffffffffu, mj, hbase + j);
            ci = fmaf(At[j * 8 + ni], mjj, ci);
        }
        // coeff i of quarter q lives in lane q*8 + i

        // ---- Clenshaw-7 at this lane's 4 query points ----
        const float tq0 = fmaf(ta, xv.x, tc);
        const float tq1 = fmaf(ta, xv.y, tc);
        const float tq2 = fmaf(ta, xv.z, tc);
        const float tq3 = fmaf(ta, xv.w, tc);
        const int q0 = min(3, max(0, __float2int_rd((tq0 - tlo) * invqw)));
        const int q1 = min(3, max(0, __float2int_rd((tq1 - tlo) * invqw)));
        const int q2 = min(3, max(0, __float2int_rd((tq2 - tlo) * invqw)));
        const int q3 = min(3, max(0, __float2int_rd((tq3 - tlo) * invqw)));
        const int b0 = q0 << 3, b1 = q1 << 3, b2 = q2 << 3, b3 = q3 << 3;
        const float c0q = fmaf((float)q0 + 0.5f, qw, tlo);
        const float c1q = fmaf((float)q1 + 0.5f, qw, tlo);
        const float c2q = fmaf((float)q2 + 0.5f, qw, tlo);
        const float c3q = fmaf((float)q3 + 0.5f, qw, tlo);
        const float s0 = fminf(1.f, fmaxf(-1.f, (tq0 - c0q) * invrq));
        const float s1 = fminf(1.f, fmaxf(-1.f, (tq1 - c1q) * invrq));
        const float s2 = fminf(1.f, fmaxf(-1.f, (tq2 - c2q) * invrq));
        const float s3 = fminf(1.f, fmaxf(-1.f, (tq3 - c3q) * invrq));
        const float d0 = 2.f * s0, d1 = 2.f * s1, d2 = 2.f * s2, d3 = 2.f * s3;

        float a1_0 = 0.f, a2_0 = 0.f;
        float a1_1 = 0.f, a2_1 = 0.f;
        float a1_2 = 0.f, a2_2 = 0.f;
        float a1_3 = 0.f, a2_3 = 0.f;
#pragma unroll
        for (int i = 7; i >= 1; i--) {
            const float cc0 = __shfl_sync(0xffffffffu, ci, b0 + i);
            const float cc1 = __shfl_sync(0xffffffffu, ci, b1 + i);
            const float cc2 = __shfl_sync(0xffffffffu, ci, b2 + i);
            const float cc3 = __shfl_sync(0xffffffffu, ci, b3 + i);
            float nb;
            nb = fmaf(d0, a1_0, cc0 - a2_0); a2_0 = a1_0; a1_0 = nb;
            nb = fmaf(d1, a1_1, cc1 - a2_1); a2_1 = a1_1; a1_1 = nb;
            nb = fmaf(d2, a1_2, cc2 - a2_2); a2_2 = a1_2; a1_2 = nb;
            nb = fmaf(d3, a1_3, cc3 - a2_3); a2_3 = a1_3; a1_3 = nb;
        }
        const float cz0 = __shfl_sync(0xffffffffu, ci, b0);
        const float cz1 = __shfl_sync(0xffffffffu, ci, b1);
        const float cz2 = __shfl_sync(0xffffffffu, ci, b2);
        const float cz3 = __shfl_sync(0xffffffffu, ci, b3);
        const float m0 = fmaf(s0, a1_0, cz0 - a2_0);
        const float m1 = fmaf(s1, a1_1, cz1 - a2_1);
        const float m2 = fmaf(s2, a1_2, cz2 - a2_2);
        const float m3 = fmaf(s3, a1_3, cz3 - a2_3);

        float msum = (m0 + m1) + (m2 + m3);
#pragma unroll
        for (int off = 16; off > 0; off >>= 1)
            msum += __shfl_xor_sync(0xffffffffu, msum, off);

        if (lane == 0)
            out[b] = fmaf(alpha, msum, beta);
    }
}

extern "C" void kernel_launch(void* const* d_in, const int* in_sizes, int n_in,
                              void* d_out, int out_size) {
    const float* x  = (const float*)d_in[0];
    const float* Wt = (const float*)d_in[1];
    const float* bt = (const float*)d_in[2];
    const float* Wq = (const float*)d_in[3];
    const float* bq = (const float*)d_in[4];
    const float* Wk = (const float*)d_in[5];
    const float* bk = (const float*)d_in[6];
    const float* Wv = (const float*)d_in[7];
    const float* bv = (const float*)d_in[8];
    const float* Wo = (const float*)d_in[9];
    const float* bo = (const float*)d_in[10];
    float* out = (float*)d_out;

    const int B = in_sizes[0] / 128;

    precompute_kernel<<<1, 192>>>(Wt, bt, Wq, bq, Wk, bk, Wv, bv, Wo, bo);

    // PDL: main kernel launches while precompute runs; synchronizes on the
    // precompute grid only right before reading g_c.
    cudaLaunchConfig_t cfg = {};
    cfg.gridDim = dim3((unsigned)((B + 15) / 16));
    cfg.blockDim = dim3(256);
    cudaLaunchAttribute attr[1];
    attr[0].id = cudaLaunchAttributeProgrammaticStreamSerialization;
    attr[0].val.programmaticStreamSerializationAllowed = 1;
    cfg.attrs = attr;
    cfg.numAttrs = 1;
    cudaLaunchKernelEx(&cfg, attn_cheb4_kernel, x, out, B);
}